// round 4
// baseline (speedup 1.0000x reference)
#include <cuda_runtime.h>
#include <math.h>

// WindAdaptivePooling: out[b,c] = mean(x[b,c,:,:]) * softmax(wind_weights)[wind_indices[b]]
// x: [64, 1280, 32, 32] fp32 = 335.5 MB single-pass stream -> HBM-bound.
// R1 53.1us (DRAM 84.9%, occ 85). R2 __ldcs neutral. R3 persistent regressed:
// regs 44 -> occ 5/SM -> DRAM 80.3%. R4: persistent + __launch_bounds__(256,8)
// + softmax hoisted to a tiny precompute kernel (scale table in device global).

__device__ float g_scale[4096];  // per-sample scale, B <= 4096

__global__ void precompute_scale_kernel(
    const int*   __restrict__ wind_indices,
    const float* __restrict__ wind_weights,
    int B, int n_winds)
{
    int b = blockIdx.x * blockDim.x + threadIdx.x;
    if (b >= B) return;
    float mx = -INFINITY;
    for (int j = 0; j < n_winds; j++) mx = fmaxf(mx, wind_weights[j]);
    float denom = 0.0f, num = 0.0f;
    int wi = wind_indices[b];
    for (int j = 0; j < n_winds; j++) {
        float e = expf(wind_weights[j] - mx);
        denom += e;
        if (j == wi) num = e;
    }
    g_scale[b] = num / denom;
}

__global__ void __launch_bounds__(256, 8) wind_pool_kernel(
    const float* __restrict__ x,
    float*       __restrict__ out,
    int n_rows,   // B*C
    int C,
    int hw)       // H*W elements per row
{
    int warp0       = (blockIdx.x * (int)blockDim.x + (int)threadIdx.x) >> 5;
    int total_warps = (gridDim.x * (int)blockDim.x) >> 5;
    int lane        = threadIdx.x & 31;
    float inv_hw    = 1.0f / (float)hw;

    for (int row = warp0; row < n_rows; row += total_warps) {
        const float4* row4 = reinterpret_cast<const float4*>(x + (size_t)row * hw);
        int n4 = hw >> 2;

        float s = 0.0f;
        if (n4 == 256) {
            // Fast path: HW=1024. 8 independent float4 loads per lane.
            float4 v0 = row4[lane + 0 * 32];
            float4 v1 = row4[lane + 1 * 32];
            float4 v2 = row4[lane + 2 * 32];
            float4 v3 = row4[lane + 3 * 32];
            float4 v4 = row4[lane + 4 * 32];
            float4 v5 = row4[lane + 5 * 32];
            float4 v6 = row4[lane + 6 * 32];
            float4 v7 = row4[lane + 7 * 32];
            s = (v0.x + v0.y + v0.z + v0.w) + (v1.x + v1.y + v1.z + v1.w)
              + (v2.x + v2.y + v2.z + v2.w) + (v3.x + v3.y + v3.z + v3.w)
              + (v4.x + v4.y + v4.z + v4.w) + (v5.x + v5.y + v5.z + v5.w)
              + (v6.x + v6.y + v6.z + v6.w) + (v7.x + v7.y + v7.z + v7.w);
        } else {
            for (int i = lane; i < n4; i += 32) {
                float4 v = row4[i];
                s += v.x + v.y + v.z + v.w;
            }
        }

        // Warp butterfly reduce
        #pragma unroll
        for (int o = 16; o > 0; o >>= 1)
            s += __shfl_xor_sync(0xFFFFFFFFu, s, o);

        if (lane == 0)
            out[row] = s * inv_hw * g_scale[row / C];
    }
}

extern "C" void kernel_launch(void* const* d_in, const int* in_sizes, int n_in,
                              void* d_out, int out_size)
{
    const float* x   = (const float*)d_in[0];
    const int*   idx = (const int*)d_in[1];
    const float* w   = (const float*)d_in[2];
    float*       out = (float*)d_out;

    int n_rows  = out_size;               // B*C
    int B       = in_sizes[1];
    int C       = n_rows / B;
    int hw      = in_sizes[0] / n_rows;   // H*W
    int n_winds = in_sizes[2];

    precompute_scale_kernel<<<(B + 63) / 64, 64>>>(idx, w, B, n_winds);

    // Persistent grid: one wave on 148 SMs x 8 CTAs/SM (regs forced <= 32)
    int blocks = 148 * 8;
    int max_blocks = (n_rows + 7) / 8;
    if (blocks > max_blocks) blocks = max_blocks;
    wind_pool_kernel<<<blocks, 256>>>(x, out, n_rows, C, hw);
}

// round 5
// speedup vs baseline: 1.0886x; 1.0886x over previous
#include <cuda_runtime.h>
#include <math.h>

// WindAdaptivePooling: out[b,c] = mean(x[b,c,:,:]) * softmax(wind_weights)[wind_indices[b]]
// x: [64, 1280, 32, 32] fp32 = 335.5 MB single-pass stream -> HBM-bound.
// History: R1 53.1us DRAM 84.9% (this kernel). R2 __ldcs: neutral (LTS path-independent).
// R3 persistent: regs 44 -> occ 5 -> 80.3%. R4 persistent+launch_bounds: MLP serialized
// by reg cap -> 77.5%. Conclusion: one-shot grid + 8xfloat4 MLP is the HBM roofline
// (~6.7 TB/s = ~85% of spec); reverting to R1 as final.

__global__ void __launch_bounds__(256) wind_pool_kernel(
    const float* __restrict__ x,
    const int*   __restrict__ wind_indices,
    const float* __restrict__ wind_weights,
    float*       __restrict__ out,
    int n_rows,   // B*C
    int C,
    int hw,       // H*W elements per row
    int n_winds)
{
    int warp = (blockIdx.x * (int)blockDim.x + (int)threadIdx.x) >> 5;
    int lane = threadIdx.x & 31;
    if (warp >= n_rows) return;

    const float4* row4 = reinterpret_cast<const float4*>(x + (size_t)warp * hw);
    int n4 = hw >> 2;

    float s = 0.0f;
    if (n4 == 256) {
        // Fast path: HW=1024. 8 fully-unrolled independent float4 loads per lane (MLP=8).
        float4 v0 = row4[lane + 0 * 32];
        float4 v1 = row4[lane + 1 * 32];
        float4 v2 = row4[lane + 2 * 32];
        float4 v3 = row4[lane + 3 * 32];
        float4 v4 = row4[lane + 4 * 32];
        float4 v5 = row4[lane + 5 * 32];
        float4 v6 = row4[lane + 6 * 32];
        float4 v7 = row4[lane + 7 * 32];
        s = (v0.x + v0.y + v0.z + v0.w) + (v1.x + v1.y + v1.z + v1.w)
          + (v2.x + v2.y + v2.z + v2.w) + (v3.x + v3.y + v3.z + v3.w)
          + (v4.x + v4.y + v4.z + v4.w) + (v5.x + v5.y + v5.z + v5.w)
          + (v6.x + v6.y + v6.z + v6.w) + (v7.x + v7.y + v7.z + v7.w);
    } else {
        for (int i = lane; i < n4; i += 32) {
            float4 v = row4[i];
            s += v.x + v.y + v.z + v.w;
        }
    }

    // Warp butterfly reduce
    #pragma unroll
    for (int o = 16; o > 0; o >>= 1)
        s += __shfl_xor_sync(0xFFFFFFFFu, s, o);

    if (lane == 0) {
        int b  = warp / C;
        int wi = wind_indices[b];
        // softmax over n_winds weights (tiny; L2-hot after first touch)
        float mx = -INFINITY;
        for (int j = 0; j < n_winds; j++) mx = fmaxf(mx, wind_weights[j]);
        float denom = 0.0f, num = 0.0f;
        for (int j = 0; j < n_winds; j++) {
            float e = expf(wind_weights[j] - mx);
            denom += e;
            if (j == wi) num = e;
        }
        out[warp] = (s / (float)hw) * (num / denom);
    }
}

extern "C" void kernel_launch(void* const* d_in, const int* in_sizes, int n_in,
                              void* d_out, int out_size)
{
    const float* x   = (const float*)d_in[0];
    const int*   idx = (const int*)d_in[1];
    const float* w   = (const float*)d_in[2];
    float*       out = (float*)d_out;

    int n_rows  = out_size;               // B*C
    int B       = in_sizes[1];
    int C       = n_rows / B;
    int hw      = in_sizes[0] / n_rows;   // H*W
    int n_winds = in_sizes[2];

    int warps_per_block = 8;              // 256 threads
    int blocks = (n_rows + warps_per_block - 1) / warps_per_block;
    wind_pool_kernel<<<blocks, warps_per_block * 32>>>(x, idx, w, out, n_rows, C, hw, n_winds);
}

// round 6
// speedup vs baseline: 1.0999x; 1.0104x over previous
#include <cuda_runtime.h>
#include <math.h>

// WindAdaptivePooling: out[b,c] = mean(x[b,c,:,:]) * softmax(wind_weights)[wind_indices[b]]
// x: [64, 1280, 32, 32] fp32 = 335.5 MB single-pass stream -> HBM-bound.
// History: R1/R5 52.7-53.1us DRAM ~84% (one-shot grid, 8x float4 MLP) = HBM plateau.
// R2 __ldcs neutral; R3/R4 persistent variants regressed (occ / reg-capped MLP).
// R6: hide the softmax tail in the load-latency shadow + lane-parallel softmax
// (1 expf + shfl instead of 8 serial expf after the reduce).

__global__ void __launch_bounds__(256) wind_pool_kernel(
    const float* __restrict__ x,
    const int*   __restrict__ wind_indices,
    const float* __restrict__ wind_weights,
    float*       __restrict__ out,
    int n_rows,   // B*C
    int C,
    int hw,       // H*W elements per row
    int n_winds)
{
    int warp = (blockIdx.x * (int)blockDim.x + (int)threadIdx.x) >> 5;
    int lane = threadIdx.x & 31;
    if (warp >= n_rows) return;

    const float4* row4 = reinterpret_cast<const float4*>(x + (size_t)warp * hw);
    int n4 = hw >> 2;

    if (n4 == 256) {
        // Issue all 8 independent float4 loads FIRST (MLP=8, front-batched).
        float4 v0 = row4[lane + 0 * 32];
        float4 v1 = row4[lane + 1 * 32];
        float4 v2 = row4[lane + 2 * 32];
        float4 v3 = row4[lane + 3 * 32];
        float4 v4 = row4[lane + 4 * 32];
        float4 v5 = row4[lane + 5 * 32];
        float4 v6 = row4[lane + 6 * 32];
        float4 v7 = row4[lane + 7 * 32];

        // Softmax scale, computed in the load-latency shadow (no dep on v*).
        // Lane-parallel: lane j owns weight j (n_winds <= 32).
        int b  = warp / C;
        int wi = wind_indices[b];               // broadcast load
        float scale;
        if (n_winds <= 32) {
            float wv = (lane < n_winds) ? wind_weights[lane] : -INFINITY;
            float mx = wv;
            #pragma unroll
            for (int o = 16; o > 0; o >>= 1)
                mx = fmaxf(mx, __shfl_xor_sync(0xFFFFFFFFu, mx, o));
            float e = (lane < n_winds) ? expf(wv - mx) : 0.0f;
            float denom = e;
            #pragma unroll
            for (int o = 16; o > 0; o >>= 1)
                denom += __shfl_xor_sync(0xFFFFFFFFu, denom, o);
            float num = __shfl_sync(0xFFFFFFFFu, e, wi);
            scale = num / denom;
        } else {
            float mx = -INFINITY;
            for (int j = 0; j < n_winds; j++) mx = fmaxf(mx, wind_weights[j]);
            float denom = 0.0f, num = 0.0f;
            for (int j = 0; j < n_winds; j++) {
                float e = expf(wind_weights[j] - mx);
                denom += e;
                if (j == wi) num = e;
            }
            scale = num / denom;
        }

        // Consume loads (first wait on memory happens here).
        float s = (v0.x + v0.y + v0.z + v0.w) + (v1.x + v1.y + v1.z + v1.w)
                + (v2.x + v2.y + v2.z + v2.w) + (v3.x + v3.y + v3.z + v3.w)
                + (v4.x + v4.y + v4.z + v4.w) + (v5.x + v5.y + v5.z + v5.w)
                + (v6.x + v6.y + v6.z + v6.w) + (v7.x + v7.y + v7.z + v7.w);

        #pragma unroll
        for (int o = 16; o > 0; o >>= 1)
            s += __shfl_xor_sync(0xFFFFFFFFu, s, o);

        if (lane == 0)
            out[warp] = (s / (float)hw) * scale;
    } else {
        // Generic path (any hw).
        float s = 0.0f;
        for (int i = lane; i < n4; i += 32) {
            float4 v = row4[i];
            s += v.x + v.y + v.z + v.w;
        }
        #pragma unroll
        for (int o = 16; o > 0; o >>= 1)
            s += __shfl_xor_sync(0xFFFFFFFFu, s, o);

        if (lane == 0) {
            int b  = warp / C;
            int wi = wind_indices[b];
            float mx = -INFINITY;
            for (int j = 0; j < n_winds; j++) mx = fmaxf(mx, wind_weights[j]);
            float denom = 0.0f, num = 0.0f;
            for (int j = 0; j < n_winds; j++) {
                float e = expf(wind_weights[j] - mx);
                denom += e;
                if (j == wi) num = e;
            }
            out[warp] = (s / (float)hw) * (num / denom);
        }
    }
}

extern "C" void kernel_launch(void* const* d_in, const int* in_sizes, int n_in,
                              void* d_out, int out_size)
{
    const float* x   = (const float*)d_in[0];
    const int*   idx = (const int*)d_in[1];
    const float* w   = (const float*)d_in[2];
    float*       out = (float*)d_out;

    int n_rows  = out_size;               // B*C
    int B       = in_sizes[1];
    int C       = n_rows / B;
    int hw      = in_sizes[0] / n_rows;   // H*W
    int n_winds = in_sizes[2];

    int warps_per_block = 8;              // 256 threads
    int blocks = (n_rows + warps_per_block - 1) / warps_per_block;
    wind_pool_kernel<<<blocks, warps_per_block * 32>>>(x, idx, w, out, n_rows, C, hw, n_winds);
}

// round 7
// speedup vs baseline: 1.1054x; 1.0049x over previous
#include <cuda_runtime.h>
#include <math.h>

// WindAdaptivePooling: out[b,c] = mean(x[b,c,:,:]) * softmax(wind_weights)[wind_indices[b]]
// x: [64, 1280, 32, 32] fp32 = 335.5 MB single-pass stream -> HBM-bound.
// History: R1/R5 52.7us (occ 87, serial softmax tail). R6 52.2us (softmax in load
// shadow, regs 57, occ 39 -- DRAM% invariant to occ). R2 __ldcs neutral; R3/R4
// persistent regressed. R7: lane-parallel softmax AFTER the reduce -- short tail
// (1 expf + shfls ~70cyc vs 300cyc serial) without holding temps across the loads.

__global__ void __launch_bounds__(256) wind_pool_kernel(
    const float* __restrict__ x,
    const int*   __restrict__ wind_indices,
    const float* __restrict__ wind_weights,
    float*       __restrict__ out,
    int n_rows,   // B*C
    int C,
    int hw,       // H*W elements per row
    int n_winds)
{
    int warp = (blockIdx.x * (int)blockDim.x + (int)threadIdx.x) >> 5;
    int lane = threadIdx.x & 31;
    if (warp >= n_rows) return;

    const float4* row4 = reinterpret_cast<const float4*>(x + (size_t)warp * hw);
    int n4 = hw >> 2;

    float s = 0.0f;
    if (n4 == 256) {
        // Fast path: HW=1024. 8 fully-unrolled independent float4 loads (MLP=8).
        float4 v0 = row4[lane + 0 * 32];
        float4 v1 = row4[lane + 1 * 32];
        float4 v2 = row4[lane + 2 * 32];
        float4 v3 = row4[lane + 3 * 32];
        float4 v4 = row4[lane + 4 * 32];
        float4 v5 = row4[lane + 5 * 32];
        float4 v6 = row4[lane + 6 * 32];
        float4 v7 = row4[lane + 7 * 32];
        s = (v0.x + v0.y + v0.z + v0.w) + (v1.x + v1.y + v1.z + v1.w)
          + (v2.x + v2.y + v2.z + v2.w) + (v3.x + v3.y + v3.z + v3.w)
          + (v4.x + v4.y + v4.z + v4.w) + (v5.x + v5.y + v5.z + v5.w)
          + (v6.x + v6.y + v6.z + v6.w) + (v7.x + v7.y + v7.z + v7.w);
    } else {
        for (int i = lane; i < n4; i += 32) {
            float4 v = row4[i];
            s += v.x + v.y + v.z + v.w;
        }
    }

    // Warp butterfly reduce of the row sum.
    #pragma unroll
    for (int o = 16; o > 0; o >>= 1)
        s += __shfl_xor_sync(0xFFFFFFFFu, s, o);

    // Lane-parallel softmax gather (temps live only AFTER loads retire -> low regs).
    int b  = warp / C;
    int wi = wind_indices[b];   // broadcast, L1/L2-hot
    float scale;
    if (n_winds <= 32) {
        float wv = (lane < n_winds) ? wind_weights[lane] : -INFINITY;
        float mx = wv;
        #pragma unroll
        for (int o = 16; o > 0; o >>= 1)
            mx = fmaxf(mx, __shfl_xor_sync(0xFFFFFFFFu, mx, o));
        float e = (lane < n_winds) ? expf(wv - mx) : 0.0f;
        float denom = e;
        #pragma unroll
        for (int o = 16; o > 0; o >>= 1)
            denom += __shfl_xor_sync(0xFFFFFFFFu, denom, o);
        float num = __shfl_sync(0xFFFFFFFFu, e, wi);
        scale = num / denom;
    } else {
        float mx = -INFINITY;
        for (int j = 0; j < n_winds; j++) mx = fmaxf(mx, wind_weights[j]);
        float denom = 0.0f, num = 0.0f;
        for (int j = 0; j < n_winds; j++) {
            float e = expf(wind_weights[j] - mx);
            denom += e;
            if (j == wi) num = e;
        }
        scale = num / denom;
    }

    if (lane == 0)
        out[warp] = (s / (float)hw) * scale;
}

extern "C" void kernel_launch(void* const* d_in, const int* in_sizes, int n_in,
                              void* d_out, int out_size)
{
    const float* x   = (const float*)d_in[0];
    const int*   idx = (const int*)d_in[1];
    const float* w   = (const float*)d_in[2];
    float*       out = (float*)d_out;

    int n_rows  = out_size;               // B*C
    int B       = in_sizes[1];
    int C       = n_rows / B;
    int hw      = in_sizes[0] / n_rows;   // H*W
    int n_winds = in_sizes[2];

    int warps_per_block = 8;              // 256 threads
    int blocks = (n_rows + warps_per_block - 1) / warps_per_block;
    wind_pool_kernel<<<blocks, warps_per_block * 32>>>(x, idx, w, out, n_rows, C, hw, n_winds);
}

// round 8
// speedup vs baseline: 1.1101x; 1.0043x over previous
#include <cuda_runtime.h>
#include <math.h>

// WindAdaptivePooling: out[b,c] = mean(x[b,c,:,:]) * softmax(wind_weights)[wind_indices[b]]
// x: [64, 1280, 32, 32] fp32 = 335.5 MB single-pass stream -> HBM-bound.
// History: R1/R5 52.7us. R2 __ldcs neutral. R3/R4 persistent regressed.
// R6 52.2us (shadow softmax, regs 57). R7 51.9us WIN: lane-parallel softmax after
// reduce -> regs 32, occ 84%, DRAM 85.3% (6.75 TB/s, best).
// R8: identical per-warp code, 512-thread blocks (16 warps) -> halve CTA churn
// (10240 -> 5120 CTAs) and per-CTA setup overhead. Last mechanistic lever.

__global__ void __launch_bounds__(512) wind_pool_kernel(
    const float* __restrict__ x,
    const int*   __restrict__ wind_indices,
    const float* __restrict__ wind_weights,
    float*       __restrict__ out,
    int n_rows,   // B*C
    int C,
    int hw,       // H*W elements per row
    int n_winds)
{
    int warp = (blockIdx.x * (int)blockDim.x + (int)threadIdx.x) >> 5;
    int lane = threadIdx.x & 31;
    if (warp >= n_rows) return;

    const float4* row4 = reinterpret_cast<const float4*>(x + (size_t)warp * hw);
    int n4 = hw >> 2;

    float s = 0.0f;
    if (n4 == 256) {
        // Fast path: HW=1024. 8 fully-unrolled independent float4 loads (MLP=8).
        float4 v0 = row4[lane + 0 * 32];
        float4 v1 = row4[lane + 1 * 32];
        float4 v2 = row4[lane + 2 * 32];
        float4 v3 = row4[lane + 3 * 32];
        float4 v4 = row4[lane + 4 * 32];
        float4 v5 = row4[lane + 5 * 32];
        float4 v6 = row4[lane + 6 * 32];
        float4 v7 = row4[lane + 7 * 32];
        s = (v0.x + v0.y + v0.z + v0.w) + (v1.x + v1.y + v1.z + v1.w)
          + (v2.x + v2.y + v2.z + v2.w) + (v3.x + v3.y + v3.z + v3.w)
          + (v4.x + v4.y + v4.z + v4.w) + (v5.x + v5.y + v5.z + v5.w)
          + (v6.x + v6.y + v6.z + v6.w) + (v7.x + v7.y + v7.z + v7.w);
    } else {
        for (int i = lane; i < n4; i += 32) {
            float4 v = row4[i];
            s += v.x + v.y + v.z + v.w;
        }
    }

    // Warp butterfly reduce of the row sum.
    #pragma unroll
    for (int o = 16; o > 0; o >>= 1)
        s += __shfl_xor_sync(0xFFFFFFFFu, s, o);

    // Lane-parallel softmax gather (temps live only AFTER loads retire -> low regs).
    int b  = warp / C;
    int wi = wind_indices[b];   // broadcast, L1/L2-hot
    float scale;
    if (n_winds <= 32) {
        float wv = (lane < n_winds) ? wind_weights[lane] : -INFINITY;
        float mx = wv;
        #pragma unroll
        for (int o = 16; o > 0; o >>= 1)
            mx = fmaxf(mx, __shfl_xor_sync(0xFFFFFFFFu, mx, o));
        float e = (lane < n_winds) ? expf(wv - mx) : 0.0f;
        float denom = e;
        #pragma unroll
        for (int o = 16; o > 0; o >>= 1)
            denom += __shfl_xor_sync(0xFFFFFFFFu, denom, o);
        float num = __shfl_sync(0xFFFFFFFFu, e, wi);
        scale = num / denom;
    } else {
        float mx = -INFINITY;
        for (int j = 0; j < n_winds; j++) mx = fmaxf(mx, wind_weights[j]);
        float denom = 0.0f, num = 0.0f;
        for (int j = 0; j < n_winds; j++) {
            float e = expf(wind_weights[j] - mx);
            denom += e;
            if (j == wi) num = e;
        }
        scale = num / denom;
    }

    if (lane == 0)
        out[warp] = (s / (float)hw) * scale;
}

extern "C" void kernel_launch(void* const* d_in, const int* in_sizes, int n_in,
                              void* d_out, int out_size)
{
    const float* x   = (const float*)d_in[0];
    const int*   idx = (const int*)d_in[1];
    const float* w   = (const float*)d_in[2];
    float*       out = (float*)d_out;

    int n_rows  = out_size;               // B*C
    int B       = in_sizes[1];
    int C       = n_rows / B;
    int hw      = in_sizes[0] / n_rows;   // H*W
    int n_winds = in_sizes[2];

    int warps_per_block = 16;             // 512 threads
    int blocks = (n_rows + warps_per_block - 1) / warps_per_block;
    wind_pool_kernel<<<blocks, warps_per_block * 32>>>(x, idx, w, out, n_rows, C, hw, n_winds);
}